// round 16
// baseline (speedup 1.0000x reference)
#include <cuda_runtime.h>
#include <cuda_fp16.h>
#include <cstdint>

#define TT   256
#define HH   30
#define INP  3
#define ROWS 64
#define NTHR 512
#define NK0  3              // K0 = 48
#define NK1  4              // K1 = 64

#define A0STR 56            // fp16 per A0 row
#define A1STR 72            // fp16 per A1 row
#define A0ROWB (A0STR*2)    // 112
#define A1ROWB (A1STR*2)    // 144
#define A0BUFB (ROWS*A0ROWB)   // 7168
#define A1BUFB (ROWS*A1ROWB)   // 9216

#define SM_BF   0
#define NTILE0  (NK0*15)                 // 45
#define NTILET  (NTILE0 + NK1*15)        // 105
#define BF_SZ   (NTILET*256)             // 26880
#define SM_A0   BF_SZ
#define SM_A1   (SM_A0 + 2*A0BUFB)       // 41216
#define SM_FC   (SM_A1 + 2*A1BUFB)       // 59648
#define SM_HFC  (SM_FC + 4098*4)         // 76040  (8-byte aligned!)
#define SM_TOTAL (SM_HFC + ROWS*32*4)    // 84232

__device__ __forceinline__ float tanh_mufu(float x){ float r; asm("tanh.approx.f32 %0,%1;":"=f"(r):"f"(x)); return r; }
__device__ __forceinline__ float sig_mufu(float x){ return fmaf(0.5f, tanh_mufu(0.5f*x), 0.5f); }
__device__ __forceinline__ uint32_t pkhf(float a, float b){
    __half2 h = __halves2half2(__float2half(a), __float2half(b));
    return *reinterpret_cast<uint32_t*>(&h);
}
__device__ __forceinline__ uint32_t smem_u32(const void* p){
    uint32_t a;
    asm("{ .reg .u64 t; cvta.to.shared.u64 t, %1; cvt.u32.u64 %0, t; }" : "=r"(a) : "l"(p));
    return a;
}
#define LDSM4(r, addr) \
    asm volatile("ldmatrix.sync.aligned.m8n8.x4.shared.b16 {%0,%1,%2,%3}, [%4];" \
        : "=r"((r)[0]),"=r"((r)[1]),"=r"((r)[2]),"=r"((r)[3]) : "r"(addr))

__device__ __forceinline__ void mma16816(float d[4], const uint32_t a[4], uint32_t b0, uint32_t b1){
    asm volatile("mma.sync.aligned.m16n8k16.row.col.f32.f16.f16.f32 "
        "{%0,%1,%2,%3},{%4,%5,%6,%7},{%8,%9},{%0,%1,%2,%3};"
        : "+f"(d[0]),"+f"(d[1]),"+f"(d[2]),"+f"(d[3])
        : "r"(a[0]),"r"(a[1]),"r"(a[2]),"r"(a[3]),"r"(b0),"r"(b1));
}
__device__ __forceinline__ float cellh(float gi, float gf, float gg, float go, float& c){
    float i_=sig_mufu(gi), f_=sig_mufu(gf), g_=tanh_mufu(gg), o_=sig_mufu(go);
    c = fmaf(f_, c, i_*g_);
    return o_ * tanh_mufu(c);
}
__device__ __forceinline__ float hhi_f(float w){ return __half2float(__float2half(w)); }

// A k-layouts (single-term fp16):
// A0: ones@0,1 | x@2-4 | pad@5 | h0@6-35 | pad to 48
// A1: ones@0,1 | h0@2-31 | h1@32-61 | pad to 64
__device__ float b0v(int k, int r, const float* Wih0, const float* Whh0,
                     const float* bih0, const float* bhh0){
    if (k < 2)  { float b=bih0[r]+bhh0[r]; float h=hhi_f(b); return k==0? h : b-h; }
    if (k < 5)  { return Wih0[r*INP + (k-2)]; }
    if (k < 6)  return 0.f;
    if (k < 36) { return Whh0[r*HH + (k-6)]; }
    return 0.f;
}
__device__ float b1v(int k, int r, const float* Wih1, const float* Whh1,
                     const float* bih1, const float* bhh1){
    if (k < 2)  { float b=bih1[r]+bhh1[r]; float h=hhi_f(b); return k==0? h : b-h; }
    if (k < 32) { return Wih1[r*HH + (k-2)]; }
    if (k < 62) { return Whh1[r*HH + (k-32)]; }
    return 0.f;
}

__global__ void __launch_bounds__(NTHR, 1)
stacked_lstm_hmma(const float* __restrict__ x,
                  const float* __restrict__ Wih0, const float* __restrict__ Whh0,
                  const float* __restrict__ bih0, const float* __restrict__ bhh0,
                  const float* __restrict__ Wih1, const float* __restrict__ Whh1,
                  const float* __restrict__ bih1, const float* __restrict__ bhh1,
                  const float* __restrict__ Wfc1, const float* __restrict__ bfc1,
                  const float* __restrict__ Wfc2, const float* __restrict__ bfc2,
                  const float* __restrict__ Wfc3, const float* __restrict__ bfc3,
                  float* __restrict__ out, int B)
{
    extern __shared__ char sm[];
    const uint32_t smb = smem_u32(sm);
    const int tid  = threadIdx.x;
    const int wid  = tid >> 5;
    const int lane = tid & 31;
    const int grp  = lane >> 2;
    const int tig  = lane & 3;
    const int rt   = wid >> 2;      // team / row tile 0..3
    const int nq   = wid & 3;
    const int ntb  = nq * 4;
    const int NTn  = (nq == 3) ? 3 : 4;
    const int row0 = rt*16 + grp;
    const int rowE = row0 + ((tig & 1) << 3);
    const int tidt = tid & 127;
    const int xrow = rt*16 + (tidt >> 3);
    const int xc   = tidt & 7;
    const bool xact = (xc < 3);
    const unsigned FULL = 0xffffffffu;

    // ================= preamble (full block) =================
    for (int i = tid; i < (2*A0BUFB + 2*A1BUFB)/4; i += NTHR)
        ((uint32_t*)(sm + SM_A0))[i] = 0u;

    uint2* bfr = (uint2*)(sm + SM_BF);
    for (int idx = tid; idx < NTILET*32; idx += NTHR) {
        int ln = idx & 31, gt = idx >> 5;
        int layer = (gt >= NTILE0);
        int lt = layer ? gt - NTILE0 : gt;
        int kt = lt / 15, nt = lt % 15;
        int n  = nt*8 + (ln >> 2);
        int j  = n >> 2, g = n & 3;
        int r  = g*HH + j;
        int k0 = kt*16 + 2*(ln & 3);
        float v00, v01, v10, v11;
        if (!layer) {
            v00=b0v(k0,r,Wih0,Whh0,bih0,bhh0);   v01=b0v(k0+1,r,Wih0,Whh0,bih0,bhh0);
            v10=b0v(k0+8,r,Wih0,Whh0,bih0,bhh0); v11=b0v(k0+9,r,Wih0,Whh0,bih0,bhh0);
        } else {
            v00=b1v(k0,r,Wih1,Whh1,bih1,bhh1);   v01=b1v(k0+1,r,Wih1,Whh1,bih1,bhh1);
            v10=b1v(k0+8,r,Wih1,Whh1,bih1,bhh1); v11=b1v(k0+9,r,Wih1,Whh1,bih1,bhh1);
        }
        bfr[gt*32 + ln] = make_uint2(pkhf(v00, v01), pkhf(v10, v11));
    }
    float* fcs = (float*)(sm + SM_FC);
    for (int i = tid; i < 64*HH; i += NTHR) fcs[i] = Wfc1[i];
    for (int i = tid; i < 64; i += NTHR)    fcs[1920 + i] = bfc1[i];
    for (int i = tid; i < 32*64; i += NTHR) fcs[1984 + i] = Wfc2[i];
    for (int i = tid; i < 32; i += NTHR) { fcs[4032 + i] = bfc2[i]; fcs[4064 + i] = Wfc3[i]; }
    if (tid == 0) fcs[4096] = bfc3[0];
    __syncthreads();

    if (tid < 2*ROWS) {
        int b = tid >> 6, row = tid & 63;
        *(uint32_t*)(sm + SM_A0 + b*A0BUFB + row*A0ROWB) = 0x3C003C00u;
        *(uint32_t*)(sm + SM_A1 + b*A1BUFB + row*A1ROWB) = 0x3C003C00u;
    }
    const float* xptr = x + ((size_t)blockIdx.x*ROWS + xrow)*TT*INP + xc;
    if (xact) {
        ((__half*)(sm + SM_A0 + xrow*A0ROWB))[2+xc] = __float2half(xptr[0]);
    }

    // B0 fragments -> registers (reused all 256 steps)
    uint2 bf0[NK0][4];
    #pragma unroll
    for (int kt = 0; kt < NK0; kt++)
        #pragma unroll
        for (int n2 = 0; n2 < 4; n2++)
            if (n2 < NTn) bf0[kt][n2] = bfr[(kt*15 + ntb + n2)*32 + lane];
    __syncthreads();

    // ldmatrix lane address bases (row = lane&15, +16B for lanes 16-31)
    const uint32_t a0base = smb + SM_A0 + (uint32_t)(rt*16 + (lane & 15))*A0ROWB + ((lane >> 4) << 4);
    const uint32_t a1base = smb + SM_A1 + (uint32_t)(rt*16 + (lane & 15))*A1ROWB + ((lane >> 4) << 4);

    // ================= per-team merged-phase recurrence =================
    float cst0[4], cst1[4];
    #pragma unroll
    for (int i = 0; i < 4; i++) { cst0[i] = 0.f; cst1[i] = 0.f; }

    float* hfc = (float*)(sm + SM_HFC);
    const int barid = rt + 1;

    for (int p = 0; p <= TT; p++) {
        const int rb = p & 1, wbuf = rb ^ 1;

        float xn = 0.f;
        const bool xload = (p + 1 < TT) && xact;
        if (xload) xn = xptr[(size_t)(p+1)*INP];

        // ---------- L0: gates0(p), p < TT ----------
        if (p < TT) {
            float acc[4][4];
            #pragma unroll
            for (int n2 = 0; n2 < 4; n2++)
                { acc[n2][0]=0.f; acc[n2][1]=0.f; acc[n2][2]=0.f; acc[n2][3]=0.f; }
            const uint32_t ab = a0base + (uint32_t)rb*A0BUFB;
            #pragma unroll
            for (int kt = 0; kt < NK0; kt++) {
                uint32_t a[4];
                LDSM4(a, ab + kt*32);
                #pragma unroll
                for (int n2 = 0; n2 < 4; n2++)
                    if (n2 < NTn) mma16816(acc[n2], a, bf0[kt][n2].x, bf0[kt][n2].y);
            }
            #pragma unroll
            for (int n2 = 0; n2 < 4; n2++) {
                if (n2 < NTn) {
                    float p0 = __shfl_xor_sync(FULL, acc[n2][0], 1);
                    float p1 = __shfl_xor_sync(FULL, acc[n2][1], 1);
                    float p2 = __shfl_xor_sync(FULL, acc[n2][2], 1);
                    float p3 = __shfl_xor_sync(FULL, acc[n2][3], 1);
                    float gi, gf, gg, go;
                    if ((tig & 1) == 0) { gi = acc[n2][0]; gf = acc[n2][1]; gg = p0; go = p1; }
                    else                { gi = p2;         gf = p3;         gg = acc[n2][2]; go = acc[n2][3]; }
                    float h = cellh(gi, gf, gg, go, cst0[n2]);
                    float hp = __shfl_xor_sync(FULL, h, 2);
                    if ((tig & 2) == 0) {
                        uint32_t hv2 = pkhf(h, hp);
                        int j = 2*(ntb + n2);
                        *(uint32_t*)(sm + SM_A0 + wbuf*A0BUFB + rowE*A0ROWB + (6+j)*2) = hv2;
                        *(uint32_t*)(sm + SM_A1 + wbuf*A1BUFB + rowE*A1ROWB + (2+j)*2) = hv2;
                    }
                }
            }
            if (xload) {
                ((__half*)(sm + SM_A0 + wbuf*A0BUFB + xrow*A0ROWB))[2+xc] = __float2half(xn);
            }
        }

        // ---------- L1: gates1(p-1), p >= 1 ----------
        if (p >= 1) {
            float acc[4][4];
            #pragma unroll
            for (int n2 = 0; n2 < 4; n2++)
                { acc[n2][0]=0.f; acc[n2][1]=0.f; acc[n2][2]=0.f; acc[n2][3]=0.f; }
            const uint32_t ab = a1base + (uint32_t)rb*A1BUFB;
            #pragma unroll
            for (int kt = 0; kt < NK1; kt++) {
                uint32_t a[4];
                LDSM4(a, ab + kt*32);
                #pragma unroll
                for (int n2 = 0; n2 < 4; n2++) {
                    if (n2 < NTn) {
                        uint2 bf = bfr[(NTILE0 + kt*15 + ntb + n2)*32 + lane];
                        mma16816(acc[n2], a, bf.x, bf.y);
                    }
                }
            }
            #pragma unroll
            for (int n2 = 0; n2 < 4; n2++) {
                if (n2 < NTn) {
                    float p0 = __shfl_xor_sync(FULL, acc[n2][0], 1);
                    float p1 = __shfl_xor_sync(FULL, acc[n2][1], 1);
                    float p2 = __shfl_xor_sync(FULL, acc[n2][2], 1);
                    float p3 = __shfl_xor_sync(FULL, acc[n2][3], 1);
                    float gi, gf, gg, go;
                    if ((tig & 1) == 0) { gi = acc[n2][0]; gf = acc[n2][1]; gg = p0; go = p1; }
                    else                { gi = p2;         gf = p3;         gg = acc[n2][2]; go = acc[n2][3]; }
                    float h = cellh(gi, gf, gg, go, cst1[n2]);
                    float hp = __shfl_xor_sync(FULL, h, 2);
                    if ((tig & 2) == 0) {
                        int j = 2*(ntb + n2);
                        *(uint32_t*)(sm + SM_A1 + wbuf*A1BUFB + rowE*A1ROWB + (32+j)*2) = pkhf(h, hp);
                        if (p == TT) *(float2*)(hfc + rowE*32 + j) = make_float2(h, hp);
                    }
                }
            }
        }
        asm volatile("bar.sync %0, %1;" :: "r"(barid), "r"(128) : "memory");
    }

    __syncthreads();   // hfc complete across all teams

    // ================= FC head (threads 0..63, fp32 h1) =================
    if (tid < ROWS) {
        float h1f[HH];
        #pragma unroll
        for (int u = 0; u < HH; u++) h1f[u] = hfc[tid*32 + u];

        float z2[32];
        #pragma unroll
        for (int o = 0; o < 32; o++) z2[o] = fcs[4032 + o];
        for (int k = 0; k < 64; k++) {
            float z = fcs[1920 + k];
            #pragma unroll
            for (int c = 0; c < HH; c++) z = fmaf(fcs[k*HH + c], h1f[c], z);
            z = fmaxf(z, 0.0f);
            #pragma unroll
            for (int o = 0; o < 32; o++) z2[o] = fmaf(fcs[1984 + o*64 + k], z, z2[o]);
        }
        float acc = fcs[4096];
        #pragma unroll
        for (int o = 0; o < 32; o++) acc = fmaf(fcs[4064 + o], fmaxf(z2[o], 0.0f), acc);
        out[(size_t)blockIdx.x*ROWS + tid] = __fdividef(1.0f, 1.0f + __expf(-acc));
    }
}

extern "C" void kernel_launch(void* const* d_in, const int* in_sizes, int n_in,
                              void* d_out, int out_size)
{
    const float* x    = (const float*)d_in[0];
    const float* Wih0 = (const float*)d_in[1];
    const float* Whh0 = (const float*)d_in[2];
    const float* bih0 = (const float*)d_in[3];
    const float* bhh0 = (const float*)d_in[4];
    const float* Wih1 = (const float*)d_in[5];
    const float* Whh1 = (const float*)d_in[6];
    const float* bih1 = (const float*)d_in[7];
    const float* bhh1 = (const float*)d_in[8];
    const float* Wfc1 = (const float*)d_in[9];
    const float* bfc1 = (const float*)d_in[10];
    const float* Wfc2 = (const float*)d_in[11];
    const float* bfc2 = (const float*)d_in[12];
    const float* Wfc3 = (const float*)d_in[13];
    const float* bfc3 = (const float*)d_in[14];
    float* out = (float*)d_out;

    int B = in_sizes[0] / (TT * INP);   // 8192
    int blocks = B / ROWS;              // 128

    cudaFuncSetAttribute(stacked_lstm_hmma,
                         cudaFuncAttributeMaxDynamicSharedMemorySize, SM_TOTAL);

    stacked_lstm_hmma<<<blocks, NTHR, SM_TOTAL>>>(x,
        Wih0, Whh0, bih0, bhh0,
        Wih1, Whh1, bih1, bhh1,
        Wfc1, bfc1, Wfc2, bfc2, Wfc3, bfc3,
        out, B);
}